// round 3
// baseline (speedup 1.0000x reference)
#include <cuda_runtime.h>

// PairWiseRankingLoss, closed form.
// gama=1 and p=sigmoid(x) in (0,1)  =>  1 + p_i - p_j > 0 for every pair, so the
// relu never clips and the masked pair-sum factorizes per row:
//   loss_b = n0*n1*gama + n1*sum_{y=0} p - n0*sum_{y=1} p
// Total = sum_b loss_b.
//
// One kernel, one block per row. Cross-block combine is a single float
// atomicAdd into g_accum; the last block (ticket) reads-and-resets it with
// atomicExch and writes the scalar output. No second barrier, no partials
// array, no broadcast.

#define B_ROWS 128
#define L_COLS 1024
#define NTHREADS 256   // 256 threads * 4 elems (float4) = 1024 = one row per block

__device__ float g_accum;           // zero at load; last block resets each launch
__device__ unsigned int g_ticket;   // zero at load; last block resets each launch

__global__ void __launch_bounds__(NTHREADS)
prl_kernel(const float* __restrict__ logit,
           const int*   __restrict__ y,
           float*       __restrict__ out)
{
    const int b = blockIdx.x;
    const int t = threadIdx.x;
    const int wid = t >> 5, lid = t & 31;

    // Vectorized coalesced loads: 4 consecutive elements per thread (2x LDG.128).
    const float4 lv = reinterpret_cast<const float4*>(logit + b * L_COLS)[t];
    const int4   yv = reinterpret_cast<const int4*>(y + b * L_COLS)[t];

    // Branchless: sum_all = sum p, sum_pos = sum y*p, cnt = sum y (as float, exact).
    float sum_all = 0.f, sum_pos = 0.f, cnt = 0.f;
    {
        float p;
        p = 1.f / (1.f + __expf(-lv.x)); sum_all += p; sum_pos = fmaf((float)yv.x, p, sum_pos); cnt += (float)yv.x;
        p = 1.f / (1.f + __expf(-lv.y)); sum_all += p; sum_pos = fmaf((float)yv.y, p, sum_pos); cnt += (float)yv.y;
        p = 1.f / (1.f + __expf(-lv.z)); sum_all += p; sum_pos = fmaf((float)yv.z, p, sum_pos); cnt += (float)yv.z;
        p = 1.f / (1.f + __expf(-lv.w)); sum_all += p; sum_pos = fmaf((float)yv.w, p, sum_pos); cnt += (float)yv.w;
    }

    // Warp reduction, 3 quantities interleaved.
    #pragma unroll
    for (int off = 16; off > 0; off >>= 1) {
        sum_all += __shfl_down_sync(0xffffffffu, sum_all, off);
        sum_pos += __shfl_down_sync(0xffffffffu, sum_pos, off);
        cnt     += __shfl_down_sync(0xffffffffu, cnt,     off);
    }

    __shared__ float s_a[8], s_p[8], s_c[8];
    if (lid == 0) { s_a[wid] = sum_all; s_p[wid] = sum_pos; s_c[wid] = cnt; }
    __syncthreads();

    // Warp 0: shuffle-reduce the 8 per-warp partials (depth 3), then t0 combines.
    if (wid == 0) {
        float a = (lid < 8) ? s_a[lid] : 0.f;
        float pp = (lid < 8) ? s_p[lid] : 0.f;
        float c  = (lid < 8) ? s_c[lid] : 0.f;
        #pragma unroll
        for (int off = 4; off > 0; off >>= 1) {
            a  += __shfl_down_sync(0xffffffffu, a,  off);
            pp += __shfl_down_sync(0xffffffffu, pp, off);
            c  += __shfl_down_sync(0xffffffffu, c,  off);
        }
        if (lid == 0) {
            const float c1 = c;
            const float c0 = (float)L_COLS - c;
            const float sneg = a - pp;
            // row loss = c0*c1*gama + c1*sum_neg - c0*sum_pos   (gama = 1)
            const float rowloss = fmaf(c1, sneg, fmaf(-c0, pp, c0 * c1));

            atomicAdd(&g_accum, rowloss);
            __threadfence();  // order accum-add before ticket-add, chip-wide
            const unsigned int ticket = atomicAdd(&g_ticket, 1u);
            if (ticket == B_ROWS - 1) {
                // All 128 accum-adds are ordered before this point.
                const float tot = atomicExch(&g_accum, 0.f);  // read + rearm in one op
                *out = tot;
                g_ticket = 0u;  // rearm ticket for the next graph replay
            }
        }
    }
}

extern "C" void kernel_launch(void* const* d_in, const int* in_sizes, int n_in,
                              void* d_out, int out_size)
{
    const float* logit = (const float*)d_in[0];
    const int*   y     = (const int*)d_in[1];
    float*       out   = (float*)d_out;
    (void)in_sizes; (void)n_in; (void)out_size;

    prl_kernel<<<B_ROWS, NTHREADS>>>(logit, y, out);
}